// round 4
// baseline (speedup 1.0000x reference)
#include <cuda_runtime.h>
#include <math.h>

#define N_NODES 50000
#define N_EDGES 800000
#define DIM 64
#define TILE_M 64
#define NP 196   // ceil(N_NODES / 256)

// Scratch (device globals)
__device__ int    g_out_cnt[N_NODES];
__device__ int    g_in_cnt[N_NODES];
__device__ int    g_row_start[N_NODES];
__device__ int    g_cursor[N_NODES];
__device__ float2 g_edata[N_EDGES];     // (src_idx bits, rsqrt(out_deg[src]))
__device__ int    g_partial[256];

// ---------------------------------------------------------------------------
// 0) Zero counters
// ---------------------------------------------------------------------------
__global__ void zero_kernel() {
    int i = blockIdx.x * blockDim.x + threadIdx.x;
    if (i < N_NODES) {
        g_out_cnt[i] = 0;
        g_in_cnt[i]  = 0;
    }
}

// ---------------------------------------------------------------------------
// 1) Histogram
// ---------------------------------------------------------------------------
__global__ void hist_kernel(const int* __restrict__ src,
                            const int* __restrict__ dst) {
    int i = blockIdx.x * blockDim.x + threadIdx.x;
    if (i < N_EDGES) {
        atomicAdd(&g_out_cnt[src[i]], 1);
        atomicAdd(&g_in_cnt[dst[i]], 1);
    }
}

// ---------------------------------------------------------------------------
// 2a) Per-block sums of in_cnt
// ---------------------------------------------------------------------------
__global__ void scanA_kernel() {
    __shared__ int sm[256];
    int t = threadIdx.x;
    int i = blockIdx.x * 256 + t;
    int v = (i < N_NODES) ? g_in_cnt[i] : 0;
    sm[t] = v;
    __syncthreads();
    #pragma unroll
    for (int off = 1; off < 256; off <<= 1) {
        int xv = (t >= off) ? sm[t - off] : 0;
        __syncthreads();
        sm[t] += xv;
        __syncthreads();
    }
    if (t == 255) g_partial[blockIdx.x] = sm[255];
}

// ---------------------------------------------------------------------------
// 2b) Full scan: each block redundantly scans the 196 partials (cheap),
//     then does its local exclusive scan. Writes row_start + cursor.
// ---------------------------------------------------------------------------
__global__ void scanC_kernel() {
    __shared__ int sp[256];
    __shared__ int sm[256];
    int t = threadIdx.x;

    int pv = (t < NP) ? g_partial[t] : 0;
    sp[t] = pv;
    __syncthreads();
    #pragma unroll
    for (int off = 1; off < 256; off <<= 1) {
        int xv = (t >= off) ? sp[t - off] : 0;
        __syncthreads();
        sp[t] += xv;
        __syncthreads();
    }
    int base = (blockIdx.x == 0) ? 0 : sp[blockIdx.x - 1];

    int i = blockIdx.x * 256 + t;
    int v = (i < N_NODES) ? g_in_cnt[i] : 0;
    sm[t] = v;
    __syncthreads();
    #pragma unroll
    for (int off = 1; off < 256; off <<= 1) {
        int xv = (t >= off) ? sm[t - off] : 0;
        __syncthreads();
        sm[t] += xv;
        __syncthreads();
    }
    if (i < N_NODES) {
        int start = base + sm[t] - v;
        g_row_start[i] = start;
        g_cursor[i]    = start;
    }
}

// ---------------------------------------------------------------------------
// 3) Fill: edata[cursor[dst]++] = (src, rsqrt(out_deg[src]))
// ---------------------------------------------------------------------------
__global__ void fill_kernel(const int* __restrict__ src,
                            const int* __restrict__ dst) {
    int i = blockIdx.x * blockDim.x + threadIdx.x;
    if (i < N_EDGES) {
        int s = src[i];
        int d = dst[i];
        float rs = rsqrtf((float)__ldg(g_out_cnt + s));
        int pos = atomicAdd(&g_cursor[d], 1);
        g_edata[pos] = make_float2(__int_as_float(s), rs);
    }
}

// ---------------------------------------------------------------------------
// 4) Fused gather + FFN. Block = 64 dst nodes, 256 threads.
//    Gather: warp w handles 8 nodes, accumulating into XOR-swizzled
//    k-major smem tile. FFN: 2 nodes x 8 cols per-thread register tile.
// ---------------------------------------------------------------------------
#define ST(k, n) sT[(k) * 64 + ((n) ^ ((k) & 31))]

__global__ void __launch_bounds__(256) fused_kernel(const float* __restrict__ x,
                                                    const float* __restrict__ w1,
                                                    const float* __restrict__ b1,
                                                    const float* __restrict__ w2,
                                                    const float* __restrict__ b2,
                                                    float* __restrict__ out) {
    __shared__ float sT[DIM * TILE_M];   // 16KB, swizzled [k][node], reused for h
    __shared__ float s_w1[DIM * DIM];    // 16KB
    __shared__ float s_w2[DIM * DIM];    // 16KB

    const int tid  = threadIdx.x;
    const int base = blockIdx.x * TILE_M;
    const int lane = tid & 31;
    const int wrp  = tid >> 5;

    // Load weights
    #pragma unroll
    for (int i = tid; i < DIM * DIM; i += 256) {
        s_w1[i] = w1[i];
        s_w2[i] = w2[i];
    }

    // ---- Gather phase: each warp fills 8 node columns of sT ----
    #pragma unroll 1
    for (int r = 0; r < 8; r++) {
        const int nl   = wrp * 8 + r;        // node-in-tile
        const int node = base + nl;

        float acc0 = 0.0f, acc1 = 0.0f;
        if (node < N_NODES) {
            const int deg   = __ldg(g_in_cnt + node);
            const int start = __ldg(g_row_start + node);
            const int end   = start + deg;
            int j = start;
            for (; j + 4 <= end; j += 4) {
                float2 e0 = __ldg(g_edata + j);
                float2 e1 = __ldg(g_edata + j + 1);
                float2 e2 = __ldg(g_edata + j + 2);
                float2 e3 = __ldg(g_edata + j + 3);
                const float* p0 = x + (size_t)__float_as_int(e0.x) * DIM;
                const float* p1 = x + (size_t)__float_as_int(e1.x) * DIM;
                const float* p2 = x + (size_t)__float_as_int(e2.x) * DIM;
                const float* p3 = x + (size_t)__float_as_int(e3.x) * DIM;
                acc0 = fmaf(__ldg(p0 + lane),      e0.y, acc0);
                acc1 = fmaf(__ldg(p0 + lane + 32), e0.y, acc1);
                acc0 = fmaf(__ldg(p1 + lane),      e1.y, acc0);
                acc1 = fmaf(__ldg(p1 + lane + 32), e1.y, acc1);
                acc0 = fmaf(__ldg(p2 + lane),      e2.y, acc0);
                acc1 = fmaf(__ldg(p2 + lane + 32), e2.y, acc1);
                acc0 = fmaf(__ldg(p3 + lane),      e3.y, acc0);
                acc1 = fmaf(__ldg(p3 + lane + 32), e3.y, acc1);
            }
            for (; j < end; j++) {
                float2 e0 = __ldg(g_edata + j);
                const float* p0 = x + (size_t)__float_as_int(e0.x) * DIM;
                acc0 = fmaf(__ldg(p0 + lane),      e0.y, acc0);
                acc1 = fmaf(__ldg(p0 + lane + 32), e0.y, acc1);
            }
            float rs_in = (deg > 0) ? rsqrtf((float)deg) : 0.0f;
            acc0 *= rs_in;
            acc1 *= rs_in;
        }
        ST(lane, nl)      = acc0;
        ST(lane + 32, nl) = acc1;
    }
    __syncthreads();

    // ---- FFN phase: thread tile = 2 nodes x 8 cols ----
    const int tn = lane;        // nodes tn, tn+32
    const int tc = wrp;         // cols tc*8 .. tc*8+7

    float acc[2][8];
    {
        float4 bj0 = __ldg((const float4*)(b1 + tc * 8));
        float4 bj1 = __ldg((const float4*)(b1 + tc * 8 + 4));
        #pragma unroll
        for (int i = 0; i < 2; i++) {
            acc[i][0] = bj0.x; acc[i][1] = bj0.y; acc[i][2] = bj0.z; acc[i][3] = bj0.w;
            acc[i][4] = bj1.x; acc[i][5] = bj1.y; acc[i][6] = bj1.z; acc[i][7] = bj1.w;
        }
    }

    #pragma unroll 8
    for (int k = 0; k < DIM; k++) {
        float a0 = ST(k, tn);
        float a1 = ST(k, tn + 32);
        float4 wv0 = *reinterpret_cast<const float4*>(&s_w1[k * DIM + tc * 8]);
        float4 wv1 = *reinterpret_cast<const float4*>(&s_w1[k * DIM + tc * 8 + 4]);
        float w[8] = {wv0.x, wv0.y, wv0.z, wv0.w, wv1.x, wv1.y, wv1.z, wv1.w};
        #pragma unroll
        for (int j = 0; j < 8; j++) {
            acc[0][j] = fmaf(a0, w[j], acc[0][j]);
            acc[1][j] = fmaf(a1, w[j], acc[1][j]);
        }
    }

    // exact GELU
    const float inv_sqrt2 = 0.70710678118654752f;
    #pragma unroll
    for (int i = 0; i < 2; i++)
        #pragma unroll
        for (int j = 0; j < 8; j++) {
            float h = acc[i][j];
            acc[i][j] = 0.5f * h * (1.0f + erff(h * inv_sqrt2));
        }

    __syncthreads();   // GEMM1 reads done before overwrite

    #pragma unroll
    for (int j = 0; j < 8; j++) {
        ST(tc * 8 + j, tn)      = acc[0][j];
        ST(tc * 8 + j, tn + 32) = acc[1][j];
    }
    __syncthreads();

    float acc2[2][8];
    {
        float4 bj0 = __ldg((const float4*)(b2 + tc * 8));
        float4 bj1 = __ldg((const float4*)(b2 + tc * 8 + 4));
        #pragma unroll
        for (int i = 0; i < 2; i++) {
            acc2[i][0] = bj0.x; acc2[i][1] = bj0.y; acc2[i][2] = bj0.z; acc2[i][3] = bj0.w;
            acc2[i][4] = bj1.x; acc2[i][5] = bj1.y; acc2[i][6] = bj1.z; acc2[i][7] = bj1.w;
        }
    }

    #pragma unroll 8
    for (int k = 0; k < DIM; k++) {
        float a0 = ST(k, tn);
        float a1 = ST(k, tn + 32);
        float4 wv0 = *reinterpret_cast<const float4*>(&s_w2[k * DIM + tc * 8]);
        float4 wv1 = *reinterpret_cast<const float4*>(&s_w2[k * DIM + tc * 8 + 4]);
        float w[8] = {wv0.x, wv0.y, wv0.z, wv0.w, wv1.x, wv1.y, wv1.z, wv1.w};
        #pragma unroll
        for (int j = 0; j < 8; j++) {
            acc2[0][j] = fmaf(a0, w[j], acc2[0][j]);
            acc2[1][j] = fmaf(a1, w[j], acc2[1][j]);
        }
    }

    #pragma unroll
    for (int i = 0; i < 2; i++) {
        int node = base + tn + 32 * i;
        if (node < N_NODES) {
            float4 v0 = make_float4(acc2[i][0], acc2[i][1], acc2[i][2], acc2[i][3]);
            float4 v1 = make_float4(acc2[i][4], acc2[i][5], acc2[i][6], acc2[i][7]);
            float* p = out + (size_t)node * DIM + tc * 8;
            *reinterpret_cast<float4*>(p)     = v0;
            *reinterpret_cast<float4*>(p + 4) = v1;
        }
    }
}

// ---------------------------------------------------------------------------
// Launcher. Inputs: x, edge_src, edge_dst, w1, b1, w2, b2
// ---------------------------------------------------------------------------
extern "C" void kernel_launch(void* const* d_in, const int* in_sizes, int n_in,
                              void* d_out, int out_size) {
    const float* x   = (const float*)d_in[0];
    const int*   src = (const int*)d_in[1];
    const int*   dst = (const int*)d_in[2];
    const float* w1  = (const float*)d_in[3];
    const float* b1  = (const float*)d_in[4];
    const float* w2  = (const float*)d_in[5];
    const float* b2  = (const float*)d_in[6];
    float* out = (float*)d_out;

    zero_kernel<<<NP, 256>>>();
    hist_kernel<<<(N_EDGES + 255) / 256, 256>>>(src, dst);
    scanA_kernel<<<NP, 256>>>();
    scanC_kernel<<<NP, 256>>>();
    fill_kernel<<<(N_EDGES + 255) / 256, 256>>>(src, dst);
    fused_kernel<<<(N_NODES + TILE_M - 1) / TILE_M, 256>>>(x, w1, b1, w2, b2, out);
}

// round 5
// speedup vs baseline: 1.3002x; 1.3002x over previous
#include <cuda_runtime.h>
#include <math.h>

#define N_NODES 50000
#define N_EDGES 800000
#define DIM 64
#define FT 128   // nodes per FFN block
#define NP 196   // ceil(N_NODES / 256)

// Scratch (device globals)
__device__ int    g_out_cnt[N_NODES];
__device__ int    g_in_cnt[N_NODES];
__device__ int    g_row_start[N_NODES];
__device__ int    g_cursor[N_NODES];
__device__ float2 g_edata[N_EDGES];     // (src_idx bits, rsqrt(out_deg[src]))
__device__ int    g_partial[256];
__device__ float  g_agg[(size_t)N_NODES * DIM];

// ---------------------------------------------------------------------------
// 0) Zero counters
// ---------------------------------------------------------------------------
__global__ void zero_kernel() {
    int i = blockIdx.x * blockDim.x + threadIdx.x;
    if (i < N_NODES) {
        g_out_cnt[i] = 0;
        g_in_cnt[i]  = 0;
    }
}

// ---------------------------------------------------------------------------
// 1) Histogram
// ---------------------------------------------------------------------------
__global__ void hist_kernel(const int* __restrict__ src,
                            const int* __restrict__ dst) {
    int i = blockIdx.x * blockDim.x + threadIdx.x;
    if (i < N_EDGES) {
        atomicAdd(&g_out_cnt[src[i]], 1);
        atomicAdd(&g_in_cnt[dst[i]], 1);
    }
}

// ---------------------------------------------------------------------------
// 2a) Per-block sums of in_cnt (shuffle reduce)
// ---------------------------------------------------------------------------
__global__ void scanA_kernel() {
    __shared__ int ws[8];
    int t = threadIdx.x, lane = t & 31, w = t >> 5;
    int i = blockIdx.x * 256 + t;
    int v = (i < N_NODES) ? g_in_cnt[i] : 0;
    #pragma unroll
    for (int off = 16; off > 0; off >>= 1)
        v += __shfl_down_sync(0xffffffffu, v, off);
    if (lane == 0) ws[w] = v;
    __syncthreads();
    if (t == 0) {
        int s = 0;
        #pragma unroll
        for (int k = 0; k < 8; k++) s += ws[k];
        g_partial[blockIdx.x] = s;
    }
}

// ---------------------------------------------------------------------------
// 2b) Full scan: each block redundantly scans 196 partials (shuffle),
//     then local exclusive scan. Writes row_start + cursor.
// ---------------------------------------------------------------------------
__global__ void scanC_kernel() {
    __shared__ int ws1[8], ws2[8];
    __shared__ int s_base;
    int t = threadIdx.x, lane = t & 31, w = t >> 5;

    // scan of partials (196 values over 256 threads)
    int pv = (t < NP) ? g_partial[t] : 0;
    int v = pv;
    #pragma unroll
    for (int off = 1; off < 32; off <<= 1) {
        int n = __shfl_up_sync(0xffffffffu, v, off);
        if (lane >= off) v += n;
    }
    if (lane == 31) ws1[w] = v;
    __syncthreads();
    if (w == 0 && lane < 8) {
        int s = ws1[lane];
        #pragma unroll
        for (int off = 1; off < 8; off <<= 1) {
            int n = __shfl_up_sync(0x000000ffu, s, off);
            if (lane >= off) s += n;
        }
        ws1[lane] = s;   // inclusive warp-sum scan
    }
    __syncthreads();
    int incl = v + ((w > 0) ? ws1[w - 1] : 0);
    if (t == blockIdx.x) s_base = incl - pv;   // exclusive prefix at blockIdx.x
    __syncthreads();

    // local exclusive scan of in_cnt
    int i = blockIdx.x * 256 + t;
    int c = (i < N_NODES) ? g_in_cnt[i] : 0;
    int v2 = c;
    #pragma unroll
    for (int off = 1; off < 32; off <<= 1) {
        int n = __shfl_up_sync(0xffffffffu, v2, off);
        if (lane >= off) v2 += n;
    }
    if (lane == 31) ws2[w] = v2;
    __syncthreads();
    if (w == 0 && lane < 8) {
        int s = ws2[lane];
        #pragma unroll
        for (int off = 1; off < 8; off <<= 1) {
            int n = __shfl_up_sync(0x000000ffu, s, off);
            if (lane >= off) s += n;
        }
        ws2[lane] = s;
    }
    __syncthreads();
    if (i < N_NODES) {
        int start = s_base + (v2 - c) + ((w > 0) ? ws2[w - 1] : 0);
        g_row_start[i] = start;
        g_cursor[i]    = start;
    }
}

// ---------------------------------------------------------------------------
// 3) Fill: edata[cursor[dst]++] = (src, rsqrt(out_deg[src]))
// ---------------------------------------------------------------------------
__global__ void fill_kernel(const int* __restrict__ src,
                            const int* __restrict__ dst) {
    int i = blockIdx.x * blockDim.x + threadIdx.x;
    if (i < N_EDGES) {
        int s = src[i];
        int d = dst[i];
        float rs = rsqrtf((float)__ldg(g_out_cnt + s));
        int pos = atomicAdd(&g_cursor[d], 1);
        g_edata[pos] = make_float2(__int_as_float(s), rs);
    }
}

// ---------------------------------------------------------------------------
// 4) Gather-aggregate: warp per dst node, register accumulation, single write.
// ---------------------------------------------------------------------------
__global__ void __launch_bounds__(256) gather_kernel(const float* __restrict__ x) {
    int node = (blockIdx.x * blockDim.x + threadIdx.x) >> 5;
    if (node >= N_NODES) return;
    const int lane = threadIdx.x & 31;

    const int deg   = __ldg(g_in_cnt + node);
    const int start = __ldg(g_row_start + node);
    const int end   = start + deg;

    float acc0 = 0.0f, acc1 = 0.0f;
    int j = start;
    for (; j + 4 <= end; j += 4) {
        float2 e0 = __ldg(g_edata + j);
        float2 e1 = __ldg(g_edata + j + 1);
        float2 e2 = __ldg(g_edata + j + 2);
        float2 e3 = __ldg(g_edata + j + 3);
        const float* p0 = x + (size_t)__float_as_int(e0.x) * DIM;
        const float* p1 = x + (size_t)__float_as_int(e1.x) * DIM;
        const float* p2 = x + (size_t)__float_as_int(e2.x) * DIM;
        const float* p3 = x + (size_t)__float_as_int(e3.x) * DIM;
        acc0 = fmaf(__ldg(p0 + lane),      e0.y, acc0);
        acc1 = fmaf(__ldg(p0 + lane + 32), e0.y, acc1);
        acc0 = fmaf(__ldg(p1 + lane),      e1.y, acc0);
        acc1 = fmaf(__ldg(p1 + lane + 32), e1.y, acc1);
        acc0 = fmaf(__ldg(p2 + lane),      e2.y, acc0);
        acc1 = fmaf(__ldg(p2 + lane + 32), e2.y, acc1);
        acc0 = fmaf(__ldg(p3 + lane),      e3.y, acc0);
        acc1 = fmaf(__ldg(p3 + lane + 32), e3.y, acc1);
    }
    for (; j < end; j++) {
        float2 e0 = __ldg(g_edata + j);
        const float* p0 = x + (size_t)__float_as_int(e0.x) * DIM;
        acc0 = fmaf(__ldg(p0 + lane),      e0.y, acc0);
        acc1 = fmaf(__ldg(p0 + lane + 32), e0.y, acc1);
    }

    float rs_in = (deg > 0) ? rsqrtf((float)deg) : 0.0f;
    g_agg[(size_t)node * DIM + lane]      = acc0 * rs_in;
    g_agg[(size_t)node * DIM + lane + 32] = acc1 * rs_in;
}

// ---------------------------------------------------------------------------
// 5) FFN: out = gelu(agg @ w1 + b1) @ w2 + b2
//    Block = 128 nodes x 64 cols, 128 threads, 8x8 thread tile.
//    Weight buffer reused (w1 then w2) -> 48KB static smem, 4 blocks/SM.
// ---------------------------------------------------------------------------
__global__ void __launch_bounds__(128) ffn_kernel(const float* __restrict__ w1,
                                                  const float* __restrict__ b1,
                                                  const float* __restrict__ w2,
                                                  const float* __restrict__ b2,
                                                  float* __restrict__ out) {
    __shared__ float sT[DIM * FT];     // [k][node] 32KB, reused for h
    __shared__ float s_w[DIM * DIM];   // 16KB, w1 then w2

    const int tid  = threadIdx.x;
    const int base = blockIdx.x * FT;
    const int tn   = tid & 15;   // node group: nodes 8*tn .. 8*tn+7
    const int tc   = tid >> 4;   // col group:  cols  8*tc .. 8*tc+7

    // load w1
    #pragma unroll
    for (int i = tid; i < DIM * DIM; i += 128) s_w[i] = w1[i];

    // transpose-fill sT: thread handles one node row
    {
        const int node = base + tid;
        #pragma unroll
        for (int k4 = 0; k4 < 16; k4++) {
            float4 v = make_float4(0.f, 0.f, 0.f, 0.f);
            if (node < N_NODES)
                v = *reinterpret_cast<const float4*>(g_agg + (size_t)node * DIM + k4 * 4);
            sT[(k4 * 4 + 0) * FT + tid] = v.x;
            sT[(k4 * 4 + 1) * FT + tid] = v.y;
            sT[(k4 * 4 + 2) * FT + tid] = v.z;
            sT[(k4 * 4 + 3) * FT + tid] = v.w;
        }
    }
    __syncthreads();

    // ---- GEMM1: h = agg @ w1 + b1 ----
    float acc[8][8];
    {
        float4 bj0 = __ldg((const float4*)(b1 + tc * 8));
        float4 bj1 = __ldg((const float4*)(b1 + tc * 8 + 4));
        #pragma unroll
        for (int i = 0; i < 8; i++) {
            acc[i][0] = bj0.x; acc[i][1] = bj0.y; acc[i][2] = bj0.z; acc[i][3] = bj0.w;
            acc[i][4] = bj1.x; acc[i][5] = bj1.y; acc[i][6] = bj1.z; acc[i][7] = bj1.w;
        }
    }

    #pragma unroll 4
    for (int k = 0; k < DIM; k++) {
        float4 a0 = *reinterpret_cast<const float4*>(&sT[k * FT + tn * 8]);
        float4 a1 = *reinterpret_cast<const float4*>(&sT[k * FT + tn * 8 + 4]);
        float4 wv0 = *reinterpret_cast<const float4*>(&s_w[k * DIM + tc * 8]);
        float4 wv1 = *reinterpret_cast<const float4*>(&s_w[k * DIM + tc * 8 + 4]);
        float a[8] = {a0.x, a0.y, a0.z, a0.w, a1.x, a1.y, a1.z, a1.w};
        float w[8] = {wv0.x, wv0.y, wv0.z, wv0.w, wv1.x, wv1.y, wv1.z, wv1.w};
        #pragma unroll
        for (int i = 0; i < 8; i++)
            #pragma unroll
            for (int j = 0; j < 8; j++)
                acc[i][j] = fmaf(a[i], w[j], acc[i][j]);
    }

    // exact GELU
    const float inv_sqrt2 = 0.70710678118654752f;
    #pragma unroll
    for (int i = 0; i < 8; i++)
        #pragma unroll
        for (int j = 0; j < 8; j++) {
            float h = acc[i][j];
            acc[i][j] = 0.5f * h * (1.0f + erff(h * inv_sqrt2));
        }

    __syncthreads();   // sT reads + s_w reads done

    // reload weights with w2; store h k-major into sT
    #pragma unroll
    for (int i = tid; i < DIM * DIM; i += 128) s_w[i] = w2[i];
    #pragma unroll
    for (int j = 0; j < 8; j++) {
        float4 h0 = make_float4(acc[0][j], acc[1][j], acc[2][j], acc[3][j]);
        float4 h1 = make_float4(acc[4][j], acc[5][j], acc[6][j], acc[7][j]);
        *reinterpret_cast<float4*>(&sT[(tc * 8 + j) * FT + tn * 8])     = h0;
        *reinterpret_cast<float4*>(&sT[(tc * 8 + j) * FT + tn * 8 + 4]) = h1;
    }
    __syncthreads();

    // ---- GEMM2: out = h @ w2 + b2 ----
    float acc2[8][8];
    {
        float4 bj0 = __ldg((const float4*)(b2 + tc * 8));
        float4 bj1 = __ldg((const float4*)(b2 + tc * 8 + 4));
        #pragma unroll
        for (int i = 0; i < 8; i++) {
            acc2[i][0] = bj0.x; acc2[i][1] = bj0.y; acc2[i][2] = bj0.z; acc2[i][3] = bj0.w;
            acc2[i][4] = bj1.x; acc2[i][5] = bj1.y; acc2[i][6] = bj1.z; acc2[i][7] = bj1.w;
        }
    }

    #pragma unroll 4
    for (int k = 0; k < DIM; k++) {
        float4 a0 = *reinterpret_cast<const float4*>(&sT[k * FT + tn * 8]);
        float4 a1 = *reinterpret_cast<const float4*>(&sT[k * FT + tn * 8 + 4]);
        float4 wv0 = *reinterpret_cast<const float4*>(&s_w[k * DIM + tc * 8]);
        float4 wv1 = *reinterpret_cast<const float4*>(&s_w[k * DIM + tc * 8 + 4]);
        float a[8] = {a0.x, a0.y, a0.z, a0.w, a1.x, a1.y, a1.z, a1.w};
        float w[8] = {wv0.x, wv0.y, wv0.z, wv0.w, wv1.x, wv1.y, wv1.z, wv1.w};
        #pragma unroll
        for (int i = 0; i < 8; i++)
            #pragma unroll
            for (int j = 0; j < 8; j++)
                acc2[i][j] = fmaf(a[i], w[j], acc2[i][j]);
    }

    // write output
    #pragma unroll
    for (int i = 0; i < 8; i++) {
        int node = base + tn * 8 + i;
        if (node < N_NODES) {
            float4 v0 = make_float4(acc2[i][0], acc2[i][1], acc2[i][2], acc2[i][3]);
            float4 v1 = make_float4(acc2[i][4], acc2[i][5], acc2[i][6], acc2[i][7]);
            float* p = out + (size_t)node * DIM + tc * 8;
            *reinterpret_cast<float4*>(p)     = v0;
            *reinterpret_cast<float4*>(p + 4) = v1;
        }
    }
}

// ---------------------------------------------------------------------------
// Launcher. Inputs: x, edge_src, edge_dst, w1, b1, w2, b2
// ---------------------------------------------------------------------------
extern "C" void kernel_launch(void* const* d_in, const int* in_sizes, int n_in,
                              void* d_out, int out_size) {
    const float* x   = (const float*)d_in[0];
    const int*   src = (const int*)d_in[1];
    const int*   dst = (const int*)d_in[2];
    const float* w1  = (const float*)d_in[3];
    const float* b1  = (const float*)d_in[4];
    const float* w2  = (const float*)d_in[5];
    const float* b2  = (const float*)d_in[6];
    float* out = (float*)d_out;

    zero_kernel<<<NP, 256>>>();
    hist_kernel<<<(N_EDGES + 255) / 256, 256>>>(src, dst);
    scanA_kernel<<<NP, 256>>>();
    scanC_kernel<<<NP, 256>>>();
    fill_kernel<<<(N_EDGES + 255) / 256, 256>>>(src, dst);
    gather_kernel<<<(N_NODES * 32 + 255) / 256, 256>>>(x);
    ffn_kernel<<<(N_NODES + FT - 1) / FT, 128>>>(w1, b1, w2, b2, out);
}